// round 11
// baseline (speedup 1.0000x reference)
#include <cuda_runtime.h>

#define NPTS 2048
#define NB   8
#define KNN  20
#define EPSV 1e-6f
#define TILE 16
#define BPB  (NPTS / TILE)   // 128 tiles per batch
#define NJOBS (NB * BPB)     // 1024 tiles total

typedef unsigned long long u64t;

__device__ __forceinline__ u64t fma2(u64t a, u64t b, u64t c) {
    u64t d;
    asm("fma.rn.f32x2 %0, %1, %2, %3;" : "=l"(d) : "l"(a), "l"(b), "l"(c));
    return d;
}
__device__ __forceinline__ u64t mul2(u64t a, u64t b) {
    u64t d;
    asm("mul.rn.f32x2 %0, %1, %2;" : "=l"(d) : "l"(a), "l"(b));
    return d;
}
__device__ __forceinline__ u64t add2(u64t a, u64t b) {
    u64t d;
    asm("add.rn.f32x2 %0, %1, %2;" : "=l"(d) : "l"(a), "l"(b));
    return d;
}
__device__ __forceinline__ u64t pack2(float lo, float hi) {
    u64t d;
    asm("mov.b64 %0, {%1, %2};" : "=l"(d) : "f"(lo), "f"(hi));
    return d;
}
__device__ __forceinline__ u64t dup2(float v) { return pack2(v, v); }
__device__ __forceinline__ void unpack2(u64t v, float& lo, float& hi) {
    asm("mov.b64 {%0, %1}, %2;" : "=f"(lo), "=f"(hi) : "l"(v));
}

// ---------------- device scratch ----------------
// feature buffers in component-major tile layout:
//   buf[ ((b*BPB + blk)*CH + ch) * 48 + comp*16 + p ]
__device__ float g_net0[NB * BPB * 64 * 48];
__device__ float g_net1[NB * BPB * 128 * 48];
__device__ float g_net2[NB * BPB * 128 * 48];

__device__ float g_Wn_pos[64 * 3];
__device__ float g_WD1[64 * 128 * 2];    // [i][o][{w,d}] normalized W1 / D1
__device__ float g_WD2[128 * 128 * 2];
__device__ float g_WD3[128 * 128 * 2];
__device__ float g_Wn2F[128 * 256];      // full normalized W2 row-major (bias part)
__device__ float g_Wn3F[128 * 256];

__device__ float g_part1[NB * BPB * 384];
__device__ float g_part2[NB * BPB * 384];
__device__ float g_part3[NB * BPB * 384];
__device__ float g_biasP2[NB * 384];
__device__ float g_biasD2[NB * 384];
__device__ float g_biasP3[NB * 384];
__device__ float g_biasD3[NB * 384];

// ---------------- prep A: row-normalize W matrices (block per row) ----------------
__global__ void __launch_bounds__(128)
prep_norm_kernel(const float* __restrict__ Wpos, const float* __restrict__ W1,
                 const float* __restrict__ W2,   const float* __restrict__ W3) {
    __shared__ float sr[128];
    int tid = threadIdx.x;
    int bx = blockIdx.x;
    if (bx == 0) {
        if (tid < 64) {
            const float* s = Wpos + tid * 3;
            float sum = s[0] + s[1] + s[2];
            for (int i = 0; i < 3; i++) g_Wn_pos[tid * 3 + i] = s[i] / sum;
        }
        return;
    }
    if (bx <= 128) {
        int r = bx - 1;
        float v = (tid < 64) ? W1[r * 64 + tid] : 0.f;
        sr[tid] = v;
        __syncthreads();
        for (int s = 64; s > 0; s >>= 1) {
            if (tid < s) sr[tid] += sr[tid + s];
            __syncthreads();
        }
        float inv = 1.f / sr[0];
        if (tid < 64) g_WD1[(tid * 128 + r) * 2] = v * inv;
        return;
    }
    const float* W = (bx <= 256) ? W2 : W3;
    float* WD = (bx <= 256) ? g_WD2 : g_WD3;
    float* WF = (bx <= 256) ? g_Wn2F : g_Wn3F;
    int r = (bx <= 256) ? (bx - 129) : (bx - 257);
    float v0 = W[r * 256 + tid];
    float v1 = W[r * 256 + tid + 128];
    sr[tid] = v0 + v1;
    __syncthreads();
    for (int s = 64; s > 0; s >>= 1) {
        if (tid < s) sr[tid] += sr[tid + s];
        __syncthreads();
    }
    float inv = 1.f / sr[0];
    float n0 = v0 * inv, n1 = v1 * inv;
    WF[r * 256 + tid] = n0;
    WF[r * 256 + tid + 128] = n1;
    WD[(tid * 128 + r) * 2] = n0;
}

// ---------------- prep B: transpose D matrices into interleaved slots ----------------
__global__ void __launch_bounds__(256)
prep_transpose_kernel(const float* __restrict__ D1, const float* __restrict__ D2,
                      const float* __restrict__ D3) {
    int idx = blockIdx.x * 256 + threadIdx.x;
    if (idx < 8192) {
        int i = idx >> 7, rr = idx & 127;
        g_WD1[(i * 128 + rr) * 2 + 1] = D1[rr * 64 + i];
    } else if (idx < 8192 + 16384) {
        int t = idx - 8192;
        int i = t >> 7, rr = t & 127;
        g_WD2[(i * 128 + rr) * 2 + 1] = D2[rr * 256 + i];
    } else if (idx < 8192 + 32768) {
        int t = idx - 8192 - 16384;
        int i = t >> 7, rr = t & 127;
        g_WD3[(i * 128 + rr) * 2 + 1] = D3[rr * 256 + i];
    }
}

// ---------------- fused kNN + edge features + pos layer + mean-k ----------------
__global__ void __launch_bounds__(256)
knn_edge_kernel(const float* __restrict__ pc, const float* __restrict__ Dpos) {
    __shared__ float4 sq[NPTS];
    __shared__ float wsh[64 * 3], dsh[64 * 3];
    __shared__ float nbx[8][24], nby[8][24], nbz[8][24];

    int b = blockIdx.y;
    const float* pb = pc + b * NPTS * 3;
    for (int m = threadIdx.x; m < NPTS; m += 256) {
        float x = pb[m * 3 + 0], y = pb[m * 3 + 1], z = pb[m * 3 + 2];
        sq[m] = make_float4(x, y, z, x * x + y * y + z * z);
    }
    for (int t = threadIdx.x; t < 192; t += 256) {
        wsh[t] = g_Wn_pos[t];
        dsh[t] = Dpos[t];
    }
    __syncthreads();

    int wid  = threadIdx.x >> 5;
    int lane = threadIdx.x & 31;
    int n = blockIdx.x * 8 + wid;
    float4 c = sq[n];

    float val = -3.4e38f;
    int   idx = 0;
    float tau = -3.4e38f;

#pragma unroll 1
    for (int r = 0; r < NPTS / 32; r++) {
        int m = r * 32 + lane;
        float4 q = sq[m];
        float d = 2.f * (c.x * q.x + c.y * q.y + c.z * q.z) - c.w - q.w;
        unsigned mask = __ballot_sync(0xffffffffu, d > tau);
        while (mask) {
            int src = __ffs(mask) - 1;
            mask &= mask - 1;
            float dc = __shfl_sync(0xffffffffu, d, src);
            if (dc > tau) {
                int mc = r * 32 + src;
                float vup = __shfl_up_sync(0xffffffffu, val, 1);
                int   iup = __shfl_up_sync(0xffffffffu, idx, 1);
                bool cw = dc > val;
                float t  = cw ? dc : val;
                int   ti = cw ? mc : idx;
                bool up = (lane > 0) && (vup < t);
                val = up ? vup : t;
                idx = up ? iup : ti;
                tau = __shfl_sync(0xffffffffu, val, KNN - 1);
            }
        }
    }

    if (lane < KNN) {
        float4 q = sq[idx];
        nbx[wid][lane] = q.x; nby[wid][lane] = q.y; nbz[wid][lane] = q.z;
    }
    __syncwarp();

    float cx = c.x, cy = c.y, cz = c.z;
    u64t cx2 = dup2(cx),  cy2 = dup2(cy),  cz2 = dup2(cz);
    u64t ncx2 = dup2(-cx), ncy2 = dup2(-cy), ncz2 = dup2(-cz);

    u64t w0_2[2], w2_2[2], d0_2[2], d2_2[2];
    u64t A2[2][3], B2[2][3];
    u64t acc[2][3];
#pragma unroll
    for (int u = 0; u < 2; u++) {
        int ch = lane + u * 32;
        float w0 = wsh[ch * 3 + 0], w1 = wsh[ch * 3 + 1], w2v = wsh[ch * 3 + 2];
        float d0 = dsh[ch * 3 + 0], d1 = dsh[ch * 3 + 1], d2v = dsh[ch * 3 + 2];
        w0_2[u] = dup2(w0); w2_2[u] = dup2(w2v);
        d0_2[u] = dup2(d0); d2_2[u] = dup2(d2v);
        float aw = w1 - w0, ad = d1 - d0;
        A2[u][0] = dup2(aw * cx); A2[u][1] = dup2(aw * cy); A2[u][2] = dup2(aw * cz);
        B2[u][0] = dup2(ad * cx); B2[u][1] = dup2(ad * cy); B2[u][2] = dup2(ad * cz);
        acc[u][0] = 0ull; acc[u][1] = 0ull; acc[u][2] = 0ull;
    }

#pragma unroll
    for (int kp = 0; kp < KNN / 2; kp++) {
        u64t nx2 = *(const u64t*)(&nbx[wid][kp * 2]);
        u64t ny2 = *(const u64t*)(&nby[wid][kp * 2]);
        u64t nz2 = *(const u64t*)(&nbz[wid][kp * 2]);
        u64t r0 = fma2(nz2, ncy2, mul2(ny2, cz2));
        u64t r1 = fma2(nx2, ncz2, mul2(nz2, cx2));
        u64t r2 = fma2(ny2, ncx2, mul2(nx2, cy2));
#pragma unroll
        for (int u = 0; u < 2; u++) {
            u64t p0 = fma2(w0_2[u], nx2, fma2(w2_2[u], r0, A2[u][0]));
            u64t p1 = fma2(w0_2[u], ny2, fma2(w2_2[u], r1, A2[u][1]));
            u64t p2 = fma2(w0_2[u], nz2, fma2(w2_2[u], r2, A2[u][2]));
            u64t q0 = fma2(d0_2[u], nx2, fma2(d2_2[u], r0, B2[u][0]));
            u64t q1 = fma2(d0_2[u], ny2, fma2(d2_2[u], r1, B2[u][1]));
            u64t q2 = fma2(d0_2[u], nz2, fma2(d2_2[u], r2, B2[u][2]));
            u64t dot2 = fma2(p2, q2, fma2(p1, q1, mul2(p0, q0)));
            u64t dns2 = fma2(q2, q2, fma2(q1, q1, mul2(q0, q0)));
            float dlo, dhi, slo, shi;
            unpack2(dot2, dlo, dhi);
            unpack2(dns2, slo, shi);
            float ntlo = (dlo < 0.f) ? -__fdividef(dlo, slo + EPSV) : 0.f;
            float nthi = (dhi < 0.f) ? -__fdividef(dhi, shi + EPSV) : 0.f;
            u64t nt2 = pack2(ntlo, nthi);
            acc[u][0] = fma2(nt2, q0, add2(acc[u][0], p0));
            acc[u][1] = fma2(nt2, q1, add2(acc[u][1], p1));
            acc[u][2] = fma2(nt2, q2, add2(acc[u][2], p2));
        }
    }

    const float inv = 1.f / (float)KNN;
    int blk = n >> 4, pp = n & 15;
#pragma unroll
    for (int u = 0; u < 2; u++) {
        int ch = lane + u * 32;
        float* dst = g_net0 + ((long)((b * BPB + blk) * 64 + ch)) * 48 + pp;
#pragma unroll
        for (int cc = 0; cc < 3; cc++) {
            float lo, hi;
            unpack2(acc[u][cc], lo, hi);
            dst[cc * 16] = (lo + hi) * inv;
        }
    }
}

// ---------------- layer64: 2 outputs/thread, reg-staged double buffer (R7 winner) ----------------
__global__ void __launch_bounds__(256)
layer64_kernel(const float* __restrict__ in, const float* __restrict__ WDg,
               float* __restrict__ out, float* __restrict__ part, int stride) {
    extern __shared__ float smem[];
    float* WDs = smem;                 // [64][128] float2
    float* xs  = WDs + 64 * 256;       // [64][3][16]
    constexpr int PF = 3;

    int tid = threadIdx.x;
    int q = tid >> 2;
    int g = tid & 3;

    for (int t = tid; t < 64 * 128; t += 256)
        ((float2*)WDs)[t] = ((const float2*)WDg)[t];

    int job = blockIdx.x;
    float4 pf[PF];
    {
        const float4* ip = (const float4*)(in + (long)job * 64 * 48);
#pragma unroll
        for (int k = 0; k < PF; k++) pf[k] = ip[tid + k * 256];
    }
    __syncthreads();

#pragma unroll 1
    for (; job < NJOBS; job += stride) {
#pragma unroll
        for (int k = 0; k < PF; k++) ((float4*)xs)[tid + k * 256] = pf[k];
        __syncthreads();

        int nj = job + stride;
        if (nj < NJOBS) {
            const float4* ip = (const float4*)(in + (long)nj * 64 * 48);
#pragma unroll
            for (int k = 0; k < PF; k++) pf[k] = ip[tid + k * 256];
        }

        u64t aP[2][3][2], aD[2][3][2];
#pragma unroll
        for (int oo = 0; oo < 2; oo++)
#pragma unroll
            for (int c = 0; c < 3; c++) {
                aP[oo][c][0] = 0ull; aP[oo][c][1] = 0ull;
                aD[oo][c][0] = 0ull; aD[oo][c][1] = 0ull;
            }

#pragma unroll 2
        for (int i = 0; i < 64; ++i) {
            float2 wd0 = ((const float2*)WDs)[i * 128 + q];
            float2 wd1 = ((const float2*)WDs)[i * 128 + 64 + q];
            u64t w0 = dup2(wd0.x), d0 = dup2(wd0.y);
            u64t w1 = dup2(wd1.x), d1 = dup2(wd1.y);
#pragma unroll
            for (int c = 0; c < 3; c++) {
                ulonglong2 X = *(const ulonglong2*)(xs + i * 48 + c * 16 + g * 4);
                aP[0][c][0] = fma2(w0, X.x, aP[0][c][0]);
                aP[0][c][1] = fma2(w0, X.y, aP[0][c][1]);
                aD[0][c][0] = fma2(d0, X.x, aD[0][c][0]);
                aD[0][c][1] = fma2(d0, X.y, aD[0][c][1]);
                aP[1][c][0] = fma2(w1, X.x, aP[1][c][0]);
                aP[1][c][1] = fma2(w1, X.y, aP[1][c][1]);
                aD[1][c][0] = fma2(d1, X.x, aD[1][c][0]);
                aD[1][c][1] = fma2(d1, X.y, aD[1][c][1]);
            }
        }

#pragma unroll
        for (int oo = 0; oo < 2; oo++) {
            int o = q + oo * 64;
            float px[3][4], dx[3][4];
#pragma unroll
            for (int c = 0; c < 3; c++) {
                unpack2(aP[oo][c][0], px[c][0], px[c][1]);
                unpack2(aP[oo][c][1], px[c][2], px[c][3]);
                unpack2(aD[oo][c][0], dx[c][0], dx[c][1]);
                unpack2(aD[oo][c][1], dx[c][2], dx[c][3]);
            }
            float qv[3][4];
            float s0 = 0.f, s1 = 0.f, s2 = 0.f;
#pragma unroll
            for (int p = 0; p < 4; p++) {
                float q0 = px[0][p], q1 = px[1][p], q2 = px[2][p];
                float e0 = dx[0][p], e1 = dx[1][p], e2 = dx[2][p];
                float dot = q0 * e0 + q1 * e1 + q2 * e2;
                if (dot < 0.f) {
                    float dns = e0 * e0 + e1 * e1 + e2 * e2;
                    float tt2 = __fdividef(dot, dns + EPSV);
                    q0 -= tt2 * e0; q1 -= tt2 * e1; q2 -= tt2 * e2;
                }
                qv[0][p] = q0; qv[1][p] = q1; qv[2][p] = q2;
                s0 += q0; s1 += q1; s2 += q2;
            }
            float4* out4 = (float4*)(out + ((long)(job * 128 + o)) * 48);
#pragma unroll
            for (int c = 0; c < 3; c++)
                out4[c * 4 + g] = make_float4(qv[c][0], qv[c][1], qv[c][2], qv[c][3]);

            s0 += __shfl_xor_sync(0xffffffffu, s0, 1);
            s1 += __shfl_xor_sync(0xffffffffu, s1, 1);
            s2 += __shfl_xor_sync(0xffffffffu, s2, 1);
            s0 += __shfl_xor_sync(0xffffffffu, s0, 2);
            s1 += __shfl_xor_sync(0xffffffffu, s1, 2);
            s2 += __shfl_xor_sync(0xffffffffu, s2, 2);
            if (g == 0) {
                float* dst = part + (long)job * 384 + o * 3;
                dst[0] = s0; dst[1] = s1; dst[2] = s2;
            }
        }
        __syncthreads();
    }
}

// ---------------- layer128: o-half split, 2 jobs/block, 2 blocks/SM ----------------
// Blocks [0,148): outputs [0,64); [148,296): outputs [64,128).
// Threads [0,128): job 2*jp; [128,256): job 2*jp+1 (shared weight half).
// Within a 128-thread half: q = lt>>2 (0..31), g = lt&3; outputs {q, q+32} of the half.
template <bool STORE>
__global__ void __launch_bounds__(256, 2)
layer128_kernel(const float* __restrict__ in, const float* __restrict__ WDg,
                const float* __restrict__ biasP, const float* __restrict__ biasD,
                float* __restrict__ out, float* __restrict__ part) {
    extern __shared__ float smem[];
    float* WDs = smem;                 // [128 i][64 ol] float2 = 64 KB
    float* xs0 = WDs + 128 * 128;      // [2][128][3][16] = 48 KB

    int hb = (blockIdx.x >= 148) ? 1 : 0;
    int j0 = blockIdx.x - hb * 148;
    int tid = threadIdx.x;
    int h  = tid >> 7;
    int lt = tid & 127;
    int q = lt >> 2;     // 0..31
    int g = lt & 3;
    float* xs = xs0 + h * 128 * 48;

    {   // stage this half's weights
        const float2* src = (const float2*)WDg;
        float2* dst = (float2*)WDs;
        for (int t = tid; t < 128 * 64; t += 256) {
            int i = t >> 6, ol = t & 63;
            dst[i * 64 + ol] = src[i * 128 + hb * 64 + ol];
        }
    }
    __syncthreads();

#pragma unroll 1
    for (int jp = j0; jp < NJOBS / 2; jp += 148) {
        int job = 2 * jp + h;

        const float4* ip = (const float4*)(in + (long)job * 128 * 48);
#pragma unroll
        for (int k = 0; k < 12; k++) ((float4*)xs)[lt + k * 128] = ip[lt + k * 128];
        __syncthreads();

        int b = job >> 7;
        u64t aP[2][3][2], aD[2][3][2];
#pragma unroll
        for (int oo = 0; oo < 2; oo++) {
            int o = hb * 64 + oo * 32 + q;
#pragma unroll
            for (int c = 0; c < 3; c++) {
                u64t bp = dup2(biasP[b * 384 + o * 3 + c]);
                u64t bd = dup2(biasD[b * 384 + o * 3 + c]);
                aP[oo][c][0] = bp; aP[oo][c][1] = bp;
                aD[oo][c][0] = bd; aD[oo][c][1] = bd;
            }
        }

#pragma unroll 2
        for (int i = 0; i < 128; ++i) {
            float2 wd0 = ((const float2*)WDs)[i * 64 + q];
            float2 wd1 = ((const float2*)WDs)[i * 64 + 32 + q];
            u64t w0 = dup2(wd0.x), d0 = dup2(wd0.y);
            u64t w1 = dup2(wd1.x), d1 = dup2(wd1.y);
#pragma unroll
            for (int c = 0; c < 3; c++) {
                ulonglong2 X = *(const ulonglong2*)(xs + i * 48 + c * 16 + g * 4);
                aP[0][c][0] = fma2(w0, X.x, aP[0][c][0]);
                aP[0][c][1] = fma2(w0, X.y, aP[0][c][1]);
                aD[0][c][0] = fma2(d0, X.x, aD[0][c][0]);
                aD[0][c][1] = fma2(d0, X.y, aD[0][c][1]);
                aP[1][c][0] = fma2(w1, X.x, aP[1][c][0]);
                aP[1][c][1] = fma2(w1, X.y, aP[1][c][1]);
                aD[1][c][0] = fma2(d1, X.x, aD[1][c][0]);
                aD[1][c][1] = fma2(d1, X.y, aD[1][c][1]);
            }
        }

#pragma unroll
        for (int oo = 0; oo < 2; oo++) {
            int o = hb * 64 + oo * 32 + q;
            float px[3][4], dx[3][4];
#pragma unroll
            for (int c = 0; c < 3; c++) {
                unpack2(aP[oo][c][0], px[c][0], px[c][1]);
                unpack2(aP[oo][c][1], px[c][2], px[c][3]);
                unpack2(aD[oo][c][0], dx[c][0], dx[c][1]);
                unpack2(aD[oo][c][1], dx[c][2], dx[c][3]);
            }
            float qv[3][4];
            float s0 = 0.f, s1 = 0.f, s2 = 0.f;
#pragma unroll
            for (int p = 0; p < 4; p++) {
                float q0 = px[0][p], q1 = px[1][p], q2 = px[2][p];
                float e0 = dx[0][p], e1 = dx[1][p], e2 = dx[2][p];
                float dot = q0 * e0 + q1 * e1 + q2 * e2;
                if (dot < 0.f) {
                    float dns = e0 * e0 + e1 * e1 + e2 * e2;
                    float tt2 = __fdividef(dot, dns + EPSV);
                    q0 -= tt2 * e0; q1 -= tt2 * e1; q2 -= tt2 * e2;
                }
                qv[0][p] = q0; qv[1][p] = q1; qv[2][p] = q2;
                s0 += q0; s1 += q1; s2 += q2;
            }
            if (STORE) {
                float4* out4 = (float4*)(out + ((long)(job * 128 + o)) * 48);
#pragma unroll
                for (int c = 0; c < 3; c++)
                    out4[c * 4 + g] = make_float4(qv[c][0], qv[c][1], qv[c][2], qv[c][3]);
            }
            s0 += __shfl_xor_sync(0xffffffffu, s0, 1);
            s1 += __shfl_xor_sync(0xffffffffu, s1, 1);
            s2 += __shfl_xor_sync(0xffffffffu, s2, 1);
            s0 += __shfl_xor_sync(0xffffffffu, s0, 2);
            s1 += __shfl_xor_sync(0xffffffffu, s1, 2);
            s2 += __shfl_xor_sync(0xffffffffu, s2, 2);
            if (g == 0) {
                float* dst = part + (long)job * 384 + o * 3;
                dst[0] = s0; dst[1] = s1; dst[2] = s2;
            }
        }
        __syncthreads();   // xs readers done before next staging
    }
}

// ---------------- bias from pooled mean ----------------
__global__ void __launch_bounds__(128)
bias_kernel(const float* __restrict__ part,
            const float* __restrict__ WnF,
            const float* __restrict__ Draw,
            float* __restrict__ biasP, float* __restrict__ biasD) {
    __shared__ float mean[384];
    int b = blockIdx.x;
    int tid = threadIdx.x;
    for (int t = tid; t < 384; t += 128) {
        float s = 0.f;
#pragma unroll 8
        for (int blk = 0; blk < BPB; blk++) s += part[((long)(b * BPB + blk)) * 384 + t];
        mean[t] = s * (1.f / (float)NPTS);
    }
    __syncthreads();
    int o = tid;
    float p0 = 0.f, p1 = 0.f, p2 = 0.f, d0 = 0.f, d1 = 0.f, d2 = 0.f;
#pragma unroll 4
    for (int i = 0; i < 128; i++) {
        float w  = WnF[o * 256 + 128 + i];
        float dd = Draw[o * 256 + 128 + i];
        float m0 = mean[i * 3 + 0], m1 = mean[i * 3 + 1], m2 = mean[i * 3 + 2];
        p0 += w * m0;  p1 += w * m1;  p2 += w * m2;
        d0 += dd * m0; d1 += dd * m1; d2 += dd * m2;
    }
    biasP[b * 384 + o * 3 + 0] = p0;
    biasP[b * 384 + o * 3 + 1] = p1;
    biasP[b * 384 + o * 3 + 2] = p2;
    biasD[b * 384 + o * 3 + 0] = d0;
    biasD[b * 384 + o * 3 + 1] = d1;
    biasD[b * 384 + o * 3 + 2] = d2;
}

// ---------------- final mean over N -> output [B,384] ----------------
__global__ void __launch_bounds__(384)
final_kernel(const float* __restrict__ part, float* __restrict__ outp) {
    int b = blockIdx.x;
    int t = threadIdx.x;
    float s = 0.f;
#pragma unroll 8
    for (int blk = 0; blk < BPB; blk++) s += part[((long)(b * BPB + blk)) * 384 + t];
    outp[b * 384 + t] = s * (1.f / (float)NPTS);
}

// ---------------- launch ----------------
extern "C" void kernel_launch(void* const* d_in, const int* in_sizes, int n_in,
                              void* d_out, int out_size) {
    const float* pc   = (const float*)d_in[0];
    const float* Wpos = (const float*)d_in[1];
    const float* Dpos = (const float*)d_in[2];
    const float* W1   = (const float*)d_in[3];
    const float* D1   = (const float*)d_in[4];
    const float* W2   = (const float*)d_in[5];
    const float* D2   = (const float*)d_in[6];
    const float* W3   = (const float*)d_in[7];
    const float* D3   = (const float*)d_in[8];
    float* outp = (float*)d_out;

    int smem1 = 64 * 256 * 4 + 64 * 48 * 4;           //  77824 B -> 2 blocks/SM
    int smem2 = 128 * 128 * 4 + 2 * 128 * 48 * 4;     // 114688 B -> 2 blocks/SM
    cudaFuncSetAttribute(layer64_kernel,
                         cudaFuncAttributeMaxDynamicSharedMemorySize, smem1);
    cudaFuncSetAttribute(layer128_kernel<true>,
                         cudaFuncAttributeMaxDynamicSharedMemorySize, smem2);
    cudaFuncSetAttribute(layer128_kernel<false>,
                         cudaFuncAttributeMaxDynamicSharedMemorySize, smem2);

    void *net0p, *net1p, *net2p;
    void *wd1, *wd2, *wd3, *wn2f, *wn3f;
    void *part1, *part2, *part3, *bp2, *bd2, *bp3, *bd3;
    cudaGetSymbolAddress(&net0p, g_net0);
    cudaGetSymbolAddress(&net1p, g_net1);
    cudaGetSymbolAddress(&net2p, g_net2);
    cudaGetSymbolAddress(&wd1, g_WD1);
    cudaGetSymbolAddress(&wd2, g_WD2);
    cudaGetSymbolAddress(&wd3, g_WD3);
    cudaGetSymbolAddress(&wn2f, g_Wn2F);
    cudaGetSymbolAddress(&wn3f, g_Wn3F);
    cudaGetSymbolAddress(&part1, g_part1);
    cudaGetSymbolAddress(&part2, g_part2);
    cudaGetSymbolAddress(&part3, g_part3);
    cudaGetSymbolAddress(&bp2, g_biasP2);
    cudaGetSymbolAddress(&bd2, g_biasD2);
    cudaGetSymbolAddress(&bp3, g_biasP3);
    cudaGetSymbolAddress(&bd3, g_biasD3);

    prep_norm_kernel<<<385, 128>>>(Wpos, W1, W2, W3);
    prep_transpose_kernel<<<160, 256>>>(D1, D2, D3);
    knn_edge_kernel<<<dim3(NPTS / 8, NB), 256>>>(pc, Dpos);

    layer64_kernel<<<296, 256, smem1>>>(
        (const float*)net0p, (const float*)wd1,
        (float*)net1p, (float*)part1, 296);

    bias_kernel<<<NB, 128>>>((const float*)part1, (const float*)wn2f, D2,
                             (float*)bp2, (float*)bd2);

    layer128_kernel<true><<<296, 256, smem2>>>(
        (const float*)net1p, (const float*)wd2,
        (const float*)bp2, (const float*)bd2, (float*)net2p, (float*)part2);

    bias_kernel<<<NB, 128>>>((const float*)part2, (const float*)wn3f, D3,
                             (float*)bp3, (float*)bd3);

    layer128_kernel<false><<<296, 256, smem2>>>(
        (const float*)net2p, (const float*)wd3,
        (const float*)bp3, (const float*)bd3, nullptr, (float*)part3);

    final_kernel<<<NB, 384>>>((const float*)part3, outp);
}

// round 12
// speedup vs baseline: 1.1649x; 1.1649x over previous
#include <cuda_runtime.h>

#define NPTS 2048
#define NB   8
#define KNN  20
#define EPSV 1e-6f
#define TILE 16
#define BPB  (NPTS / TILE)   // 128 tiles per batch
#define NJOBS (NB * BPB)     // 1024 tiles total

typedef unsigned long long u64t;

__device__ __forceinline__ u64t fma2(u64t a, u64t b, u64t c) {
    u64t d;
    asm("fma.rn.f32x2 %0, %1, %2, %3;" : "=l"(d) : "l"(a), "l"(b), "l"(c));
    return d;
}
__device__ __forceinline__ u64t mul2(u64t a, u64t b) {
    u64t d;
    asm("mul.rn.f32x2 %0, %1, %2;" : "=l"(d) : "l"(a), "l"(b));
    return d;
}
__device__ __forceinline__ u64t add2(u64t a, u64t b) {
    u64t d;
    asm("add.rn.f32x2 %0, %1, %2;" : "=l"(d) : "l"(a), "l"(b));
    return d;
}
__device__ __forceinline__ u64t pack2(float lo, float hi) {
    u64t d;
    asm("mov.b64 %0, {%1, %2};" : "=l"(d) : "f"(lo), "f"(hi));
    return d;
}
__device__ __forceinline__ u64t dup2(float v) { return pack2(v, v); }
__device__ __forceinline__ void unpack2(u64t v, float& lo, float& hi) {
    asm("mov.b64 {%0, %1}, %2;" : "=f"(lo), "=f"(hi) : "l"(v));
}

// ---------------- device scratch ----------------
// feature buffers in component-major tile layout:
//   buf[ ((b*BPB + blk)*CH + ch) * 48 + comp*16 + p ]
__device__ float g_net0[NB * BPB * 64 * 48];
__device__ float g_net1[NB * BPB * 128 * 48];
__device__ float g_net2[NB * BPB * 128 * 48];

__device__ float g_Wn_pos[64 * 3];
__device__ float g_WD1[64 * 128 * 2];    // [i][o][{w,d}] normalized W1 / D1
__device__ float g_WD2[128 * 128 * 2];   // W2/D2 cols [0,128)
__device__ float g_WD3[128 * 128 * 2];
__device__ float g_WD2B[128 * 128 * 2];  // W2/D2 cols [128,256) (pooled half), [i][o][{w,d}]
__device__ float g_WD3B[128 * 128 * 2];

__device__ float g_part1[NB * BPB * 384];
__device__ float g_part2[NB * BPB * 384];
__device__ float g_part3[NB * BPB * 384];
__device__ float g_biasP2[NB * 384];
__device__ float g_biasD2[NB * 384];
__device__ float g_biasP3[NB * 384];
__device__ float g_biasD3[NB * 384];

// ---------------- prep A: row-normalize W matrices (block per row) ----------------
__global__ void __launch_bounds__(128)
prep_norm_kernel(const float* __restrict__ Wpos, const float* __restrict__ W1,
                 const float* __restrict__ W2,   const float* __restrict__ W3) {
    __shared__ float sr[128];
    int tid = threadIdx.x;
    int bx = blockIdx.x;
    if (bx == 0) {
        if (tid < 64) {
            const float* s = Wpos + tid * 3;
            float sum = s[0] + s[1] + s[2];
            for (int i = 0; i < 3; i++) g_Wn_pos[tid * 3 + i] = s[i] / sum;
        }
        return;
    }
    if (bx <= 128) {
        int r = bx - 1;
        float v = (tid < 64) ? W1[r * 64 + tid] : 0.f;
        sr[tid] = v;
        __syncthreads();
        for (int s = 64; s > 0; s >>= 1) {
            if (tid < s) sr[tid] += sr[tid + s];
            __syncthreads();
        }
        float inv = 1.f / sr[0];
        if (tid < 64) g_WD1[(tid * 128 + r) * 2] = v * inv;
        return;
    }
    const float* W  = (bx <= 256) ? W2 : W3;
    float* WD  = (bx <= 256) ? g_WD2  : g_WD3;
    float* WDB = (bx <= 256) ? g_WD2B : g_WD3B;
    int r = (bx <= 256) ? (bx - 129) : (bx - 257);
    float v0 = W[r * 256 + tid];
    float v1 = W[r * 256 + tid + 128];
    sr[tid] = v0 + v1;
    __syncthreads();
    for (int s = 64; s > 0; s >>= 1) {
        if (tid < s) sr[tid] += sr[tid + s];
        __syncthreads();
    }
    float inv = 1.f / sr[0];
    WD [(tid * 128 + r) * 2] = v0 * inv;
    WDB[(tid * 128 + r) * 2] = v1 * inv;
}

// ---------------- prep B: transpose D matrices into interleaved slots ----------------
__global__ void __launch_bounds__(256)
prep_transpose_kernel(const float* __restrict__ D1, const float* __restrict__ D2,
                      const float* __restrict__ D3) {
    int idx = blockIdx.x * 256 + threadIdx.x;
    if (idx < 8192) {                                   // D1: [128][64]
        int i = idx >> 7, rr = idx & 127;
        g_WD1[(i * 128 + rr) * 2 + 1] = D1[rr * 64 + i];
    } else if (idx < 8192 + 16384) {                    // D2 cols [0,128)
        int t = idx - 8192;
        int i = t >> 7, rr = t & 127;
        g_WD2[(i * 128 + rr) * 2 + 1] = D2[rr * 256 + i];
    } else if (idx < 8192 + 32768) {                    // D2 cols [128,256)
        int t = idx - 8192 - 16384;
        int i = t >> 7, rr = t & 127;
        g_WD2B[(i * 128 + rr) * 2 + 1] = D2[rr * 256 + 128 + i];
    } else if (idx < 8192 + 32768 + 16384) {            // D3 cols [0,128)
        int t = idx - 8192 - 32768;
        int i = t >> 7, rr = t & 127;
        g_WD3[(i * 128 + rr) * 2 + 1] = D3[rr * 256 + i];
    } else if (idx < 8192 + 65536) {                    // D3 cols [128,256)
        int t = idx - 8192 - 32768 - 16384;
        int i = t >> 7, rr = t & 127;
        g_WD3B[(i * 128 + rr) * 2 + 1] = D3[rr * 256 + 128 + i];
    }
}

// ---------------- fused kNN + edge features + pos layer + mean-k (R7 winner) ----------------
__global__ void __launch_bounds__(256)
knn_edge_kernel(const float* __restrict__ pc, const float* __restrict__ Dpos) {
    __shared__ float4 sq[NPTS];
    __shared__ float wsh[64 * 3], dsh[64 * 3];
    __shared__ float nbx[8][24], nby[8][24], nbz[8][24];

    int b = blockIdx.y;
    const float* pb = pc + b * NPTS * 3;
    for (int m = threadIdx.x; m < NPTS; m += 256) {
        float x = pb[m * 3 + 0], y = pb[m * 3 + 1], z = pb[m * 3 + 2];
        sq[m] = make_float4(x, y, z, x * x + y * y + z * z);
    }
    for (int t = threadIdx.x; t < 192; t += 256) {
        wsh[t] = g_Wn_pos[t];
        dsh[t] = Dpos[t];
    }
    __syncthreads();

    int wid  = threadIdx.x >> 5;
    int lane = threadIdx.x & 31;
    int n = blockIdx.x * 8 + wid;
    float4 c = sq[n];

    float val = -3.4e38f;
    int   idx = 0;
    float tau = -3.4e38f;

#pragma unroll 1
    for (int r = 0; r < NPTS / 32; r++) {
        int m = r * 32 + lane;
        float4 q = sq[m];
        float d = 2.f * (c.x * q.x + c.y * q.y + c.z * q.z) - c.w - q.w;
        unsigned mask = __ballot_sync(0xffffffffu, d > tau);
        while (mask) {
            int src = __ffs(mask) - 1;
            mask &= mask - 1;
            float dc = __shfl_sync(0xffffffffu, d, src);
            if (dc > tau) {
                int mc = r * 32 + src;
                float vup = __shfl_up_sync(0xffffffffu, val, 1);
                int   iup = __shfl_up_sync(0xffffffffu, idx, 1);
                bool cw = dc > val;
                float t  = cw ? dc : val;
                int   ti = cw ? mc : idx;
                bool up = (lane > 0) && (vup < t);
                val = up ? vup : t;
                idx = up ? iup : ti;
                tau = __shfl_sync(0xffffffffu, val, KNN - 1);
            }
        }
    }

    if (lane < KNN) {
        float4 q = sq[idx];
        nbx[wid][lane] = q.x; nby[wid][lane] = q.y; nbz[wid][lane] = q.z;
    }
    __syncwarp();

    float cx = c.x, cy = c.y, cz = c.z;
    u64t cx2 = dup2(cx),  cy2 = dup2(cy),  cz2 = dup2(cz);
    u64t ncx2 = dup2(-cx), ncy2 = dup2(-cy), ncz2 = dup2(-cz);

    u64t w0_2[2], w2_2[2], d0_2[2], d2_2[2];
    u64t A2[2][3], B2[2][3];
    u64t acc[2][3];
#pragma unroll
    for (int u = 0; u < 2; u++) {
        int ch = lane + u * 32;
        float w0 = wsh[ch * 3 + 0], w1 = wsh[ch * 3 + 1], w2v = wsh[ch * 3 + 2];
        float d0 = dsh[ch * 3 + 0], d1 = dsh[ch * 3 + 1], d2v = dsh[ch * 3 + 2];
        w0_2[u] = dup2(w0); w2_2[u] = dup2(w2v);
        d0_2[u] = dup2(d0); d2_2[u] = dup2(d2v);
        float aw = w1 - w0, ad = d1 - d0;
        A2[u][0] = dup2(aw * cx); A2[u][1] = dup2(aw * cy); A2[u][2] = dup2(aw * cz);
        B2[u][0] = dup2(ad * cx); B2[u][1] = dup2(ad * cy); B2[u][2] = dup2(ad * cz);
        acc[u][0] = 0ull; acc[u][1] = 0ull; acc[u][2] = 0ull;
    }

#pragma unroll
    for (int kp = 0; kp < KNN / 2; kp++) {
        u64t nx2 = *(const u64t*)(&nbx[wid][kp * 2]);
        u64t ny2 = *(const u64t*)(&nby[wid][kp * 2]);
        u64t nz2 = *(const u64t*)(&nbz[wid][kp * 2]);
        u64t r0 = fma2(nz2, ncy2, mul2(ny2, cz2));
        u64t r1 = fma2(nx2, ncz2, mul2(nz2, cx2));
        u64t r2 = fma2(ny2, ncx2, mul2(nx2, cy2));
#pragma unroll
        for (int u = 0; u < 2; u++) {
            u64t p0 = fma2(w0_2[u], nx2, fma2(w2_2[u], r0, A2[u][0]));
            u64t p1 = fma2(w0_2[u], ny2, fma2(w2_2[u], r1, A2[u][1]));
            u64t p2 = fma2(w0_2[u], nz2, fma2(w2_2[u], r2, A2[u][2]));
            u64t q0 = fma2(d0_2[u], nx2, fma2(d2_2[u], r0, B2[u][0]));
            u64t q1 = fma2(d0_2[u], ny2, fma2(d2_2[u], r1, B2[u][1]));
            u64t q2 = fma2(d0_2[u], nz2, fma2(d2_2[u], r2, B2[u][2]));
            u64t dot2 = fma2(p2, q2, fma2(p1, q1, mul2(p0, q0)));
            u64t dns2 = fma2(q2, q2, fma2(q1, q1, mul2(q0, q0)));
            float dlo, dhi, slo, shi;
            unpack2(dot2, dlo, dhi);
            unpack2(dns2, slo, shi);
            float ntlo = (dlo < 0.f) ? -__fdividef(dlo, slo + EPSV) : 0.f;
            float nthi = (dhi < 0.f) ? -__fdividef(dhi, shi + EPSV) : 0.f;
            u64t nt2 = pack2(ntlo, nthi);
            acc[u][0] = fma2(nt2, q0, add2(acc[u][0], p0));
            acc[u][1] = fma2(nt2, q1, add2(acc[u][1], p1));
            acc[u][2] = fma2(nt2, q2, add2(acc[u][2], p2));
        }
    }

    const float inv = 1.f / (float)KNN;
    int blk = n >> 4, pp = n & 15;
#pragma unroll
    for (int u = 0; u < 2; u++) {
        int ch = lane + u * 32;
        float* dst = g_net0 + ((long)((b * BPB + blk) * 64 + ch)) * 48 + pp;
#pragma unroll
        for (int cc = 0; cc < 3; cc++) {
            float lo, hi;
            unpack2(acc[u][cc], lo, hi);
            dst[cc * 16] = (lo + hi) * inv;
        }
    }
}

// ---------------- VNT layer: 2 outputs/thread, reg-staged double buffer (R7 winner) ----------------
template <int IN_CH, bool STORE, bool BIAS>
__global__ void __launch_bounds__(256)
layer_kernel(const float* __restrict__ in, const float* __restrict__ WDg,
             const float* __restrict__ biasP, const float* __restrict__ biasD,
             float* __restrict__ out, float* __restrict__ part, int stride) {
    extern __shared__ float smem[];
    float* WDs = smem;                 // [IN_CH][128] float2
    float* xs  = WDs + IN_CH * 256;    // [IN_CH][3][16]
    constexpr int PF = IN_CH * 12 / 256;

    int tid = threadIdx.x;
    int q = tid >> 2;
    int g = tid & 3;

    for (int t = tid; t < IN_CH * 128; t += 256)
        ((float2*)WDs)[t] = ((const float2*)WDg)[t];

    int job = blockIdx.x;
    float4 pf[PF];
    {
        const float4* ip = (const float4*)(in + (long)job * IN_CH * 48);
#pragma unroll
        for (int k = 0; k < PF; k++) pf[k] = ip[tid + k * 256];
    }
    __syncthreads();

#pragma unroll 1
    for (; job < NJOBS; job += stride) {
#pragma unroll
        for (int k = 0; k < PF; k++) ((float4*)xs)[tid + k * 256] = pf[k];
        __syncthreads();

        int nj = job + stride;
        if (nj < NJOBS) {
            const float4* ip = (const float4*)(in + (long)nj * IN_CH * 48);
#pragma unroll
            for (int k = 0; k < PF; k++) pf[k] = ip[tid + k * 256];
        }

        int b = job >> 7;
        u64t aP[2][3][2], aD[2][3][2];
#pragma unroll
        for (int oo = 0; oo < 2; oo++) {
            int o = q + oo * 64;
#pragma unroll
            for (int c = 0; c < 3; c++) {
                u64t bp = 0ull, bd = 0ull;
                if (BIAS) {
                    bp = dup2(biasP[b * 384 + o * 3 + c]);
                    bd = dup2(biasD[b * 384 + o * 3 + c]);
                }
                aP[oo][c][0] = bp; aP[oo][c][1] = bp;
                aD[oo][c][0] = bd; aD[oo][c][1] = bd;
            }
        }

#pragma unroll 2
        for (int i = 0; i < IN_CH; ++i) {
            float2 wd0 = ((const float2*)WDs)[i * 128 + q];
            float2 wd1 = ((const float2*)WDs)[i * 128 + 64 + q];
            u64t w0 = dup2(wd0.x), d0 = dup2(wd0.y);
            u64t w1 = dup2(wd1.x), d1 = dup2(wd1.y);
#pragma unroll
            for (int c = 0; c < 3; c++) {
                ulonglong2 X = *(const ulonglong2*)(xs + i * 48 + c * 16 + g * 4);
                aP[0][c][0] = fma2(w0, X.x, aP[0][c][0]);
                aP[0][c][1] = fma2(w0, X.y, aP[0][c][1]);
                aD[0][c][0] = fma2(d0, X.x, aD[0][c][0]);
                aD[0][c][1] = fma2(d0, X.y, aD[0][c][1]);
                aP[1][c][0] = fma2(w1, X.x, aP[1][c][0]);
                aP[1][c][1] = fma2(w1, X.y, aP[1][c][1]);
                aD[1][c][0] = fma2(d1, X.x, aD[1][c][0]);
                aD[1][c][1] = fma2(d1, X.y, aD[1][c][1]);
            }
        }

#pragma unroll
        for (int oo = 0; oo < 2; oo++) {
            int o = q + oo * 64;
            float px[3][4], dx[3][4];
#pragma unroll
            for (int c = 0; c < 3; c++) {
                unpack2(aP[oo][c][0], px[c][0], px[c][1]);
                unpack2(aP[oo][c][1], px[c][2], px[c][3]);
                unpack2(aD[oo][c][0], dx[c][0], dx[c][1]);
                unpack2(aD[oo][c][1], dx[c][2], dx[c][3]);
            }
            float qv[3][4];
            float s0 = 0.f, s1 = 0.f, s2 = 0.f;
#pragma unroll
            for (int p = 0; p < 4; p++) {
                float q0 = px[0][p], q1 = px[1][p], q2 = px[2][p];
                float e0 = dx[0][p], e1 = dx[1][p], e2 = dx[2][p];
                float dot = q0 * e0 + q1 * e1 + q2 * e2;
                if (dot < 0.f) {
                    float dns = e0 * e0 + e1 * e1 + e2 * e2;
                    float tt2 = __fdividef(dot, dns + EPSV);
                    q0 -= tt2 * e0; q1 -= tt2 * e1; q2 -= tt2 * e2;
                }
                qv[0][p] = q0; qv[1][p] = q1; qv[2][p] = q2;
                s0 += q0; s1 += q1; s2 += q2;
            }
            if (STORE) {
                float4* out4 = (float4*)(out + ((long)(job * 128 + o)) * 48);
#pragma unroll
                for (int c = 0; c < 3; c++)
                    out4[c * 4 + g] = make_float4(qv[c][0], qv[c][1], qv[c][2], qv[c][3]);
            }
            s0 += __shfl_xor_sync(0xffffffffu, s0, 1);
            s1 += __shfl_xor_sync(0xffffffffu, s1, 1);
            s2 += __shfl_xor_sync(0xffffffffu, s2, 1);
            s0 += __shfl_xor_sync(0xffffffffu, s0, 2);
            s1 += __shfl_xor_sync(0xffffffffu, s1, 2);
            s2 += __shfl_xor_sync(0xffffffffu, s2, 2);
            if (g == 0) {
                float* dst = part + (long)job * 384 + o * 3;
                dst[0] = s0; dst[1] = s1; dst[2] = s2;
            }
        }
        __syncthreads();
    }
}

// ---------------- bias from pooled mean: coalesced interleaved weights ----------------
// WDb layout [i][o][{w,d}] for the pooled input half -> one coalesced float2 per (i,o).
__global__ void __launch_bounds__(128)
bias_kernel(const float* __restrict__ part, const float* __restrict__ WDb,
            float* __restrict__ biasP, float* __restrict__ biasD) {
    __shared__ float mean[384];
    int b = blockIdx.x;
    int tid = threadIdx.x;  // 128
    for (int t = tid; t < 384; t += 128) {
        float s = 0.f;
#pragma unroll 16
        for (int blk = 0; blk < BPB; blk++) s += part[((long)(b * BPB + blk)) * 384 + t];
        mean[t] = s * (1.f / (float)NPTS);
    }
    __syncthreads();
    int o = tid;
    float p0 = 0.f, p1 = 0.f, p2 = 0.f, d0 = 0.f, d1 = 0.f, d2 = 0.f;
#pragma unroll 8
    for (int i = 0; i < 128; i++) {
        float2 wd = ((const float2*)WDb)[i * 128 + o];
        float m0 = mean[i * 3 + 0], m1 = mean[i * 3 + 1], m2 = mean[i * 3 + 2];
        p0 += wd.x * m0;  p1 += wd.x * m1;  p2 += wd.x * m2;
        d0 += wd.y * m0;  d1 += wd.y * m1;  d2 += wd.y * m2;
    }
    biasP[b * 384 + o * 3 + 0] = p0;
    biasP[b * 384 + o * 3 + 1] = p1;
    biasP[b * 384 + o * 3 + 2] = p2;
    biasD[b * 384 + o * 3 + 0] = d0;
    biasD[b * 384 + o * 3 + 1] = d1;
    biasD[b * 384 + o * 3 + 2] = d2;
}

// ---------------- final mean over N -> output [B,384] ----------------
__global__ void __launch_bounds__(384)
final_kernel(const float* __restrict__ part, float* __restrict__ outp) {
    int b = blockIdx.x;
    int t = threadIdx.x;
    float s = 0.f;
#pragma unroll 16
    for (int blk = 0; blk < BPB; blk++) s += part[((long)(b * BPB + blk)) * 384 + t];
    outp[b * 384 + t] = s * (1.f / (float)NPTS);
}

// ---------------- launch ----------------
extern "C" void kernel_launch(void* const* d_in, const int* in_sizes, int n_in,
                              void* d_out, int out_size) {
    const float* pc   = (const float*)d_in[0];
    const float* Wpos = (const float*)d_in[1];
    const float* Dpos = (const float*)d_in[2];
    const float* W1   = (const float*)d_in[3];
    const float* D1   = (const float*)d_in[4];
    const float* W2   = (const float*)d_in[5];
    const float* D2   = (const float*)d_in[6];
    const float* W3   = (const float*)d_in[7];
    const float* D3   = (const float*)d_in[8];
    float* outp = (float*)d_out;

    int smem1 = 64 * 256 * 4 + 64 * 48 * 4;     //  77824 B -> 2 blocks/SM
    int smem2 = 128 * 256 * 4 + 128 * 48 * 4;   // 155648 B -> 1 block/SM
    cudaFuncSetAttribute(layer_kernel<64, true, false>,
                         cudaFuncAttributeMaxDynamicSharedMemorySize, smem1);
    cudaFuncSetAttribute(layer_kernel<128, true, true>,
                         cudaFuncAttributeMaxDynamicSharedMemorySize, smem2);
    cudaFuncSetAttribute(layer_kernel<128, false, true>,
                         cudaFuncAttributeMaxDynamicSharedMemorySize, smem2);

    void *net0p, *net1p, *net2p;
    void *wd1, *wd2, *wd3, *wd2b, *wd3b;
    void *part1, *part2, *part3, *bp2, *bd2, *bp3, *bd3;
    cudaGetSymbolAddress(&net0p, g_net0);
    cudaGetSymbolAddress(&net1p, g_net1);
    cudaGetSymbolAddress(&net2p, g_net2);
    cudaGetSymbolAddress(&wd1, g_WD1);
    cudaGetSymbolAddress(&wd2, g_WD2);
    cudaGetSymbolAddress(&wd3, g_WD3);
    cudaGetSymbolAddress(&wd2b, g_WD2B);
    cudaGetSymbolAddress(&wd3b, g_WD3B);
    cudaGetSymbolAddress(&part1, g_part1);
    cudaGetSymbolAddress(&part2, g_part2);
    cudaGetSymbolAddress(&part3, g_part3);
    cudaGetSymbolAddress(&bp2, g_biasP2);
    cudaGetSymbolAddress(&bd2, g_biasD2);
    cudaGetSymbolAddress(&bp3, g_biasP3);
    cudaGetSymbolAddress(&bd3, g_biasD3);

    prep_norm_kernel<<<385, 128>>>(Wpos, W1, W2, W3);
    prep_transpose_kernel<<<288, 256>>>(D1, D2, D3);
    knn_edge_kernel<<<dim3(NPTS / 8, NB), 256>>>(pc, Dpos);

    layer_kernel<64, true, false><<<296, 256, smem1>>>(
        (const float*)net0p, (const float*)wd1,
        nullptr, nullptr, (float*)net1p, (float*)part1, 296);

    bias_kernel<<<NB, 128>>>((const float*)part1, (const float*)wd2b,
                             (float*)bp2, (float*)bd2);

    layer_kernel<128, true, true><<<148, 256, smem2>>>(
        (const float*)net1p, (const float*)wd2,
        (const float*)bp2, (const float*)bd2, (float*)net2p, (float*)part2, 148);

    bias_kernel<<<NB, 128>>>((const float*)part2, (const float*)wd3b,
                             (float*)bp3, (float*)bd3);

    layer_kernel<128, false, true><<<148, 256, smem2>>>(
        (const float*)net2p, (const float*)wd3,
        (const float*)bp3, (const float*)bd3, nullptr, (float*)part3, 148);

    final_kernel<<<NB, 384>>>((const float*)part3, outp);
}

// round 13
// speedup vs baseline: 1.2082x; 1.0372x over previous
#include <cuda_runtime.h>

#define NPTS 2048
#define NB   8
#define KNN  20
#define EPSV 1e-6f
#define TILE 16
#define BPB  (NPTS / TILE)   // 128 tiles per batch
#define NJOBS (NB * BPB)     // 1024 tiles total

typedef unsigned long long u64t;

__device__ __forceinline__ u64t fma2(u64t a, u64t b, u64t c) {
    u64t d;
    asm("fma.rn.f32x2 %0, %1, %2, %3;" : "=l"(d) : "l"(a), "l"(b), "l"(c));
    return d;
}
__device__ __forceinline__ u64t mul2(u64t a, u64t b) {
    u64t d;
    asm("mul.rn.f32x2 %0, %1, %2;" : "=l"(d) : "l"(a), "l"(b));
    return d;
}
__device__ __forceinline__ u64t add2(u64t a, u64t b) {
    u64t d;
    asm("add.rn.f32x2 %0, %1, %2;" : "=l"(d) : "l"(a), "l"(b));
    return d;
}
__device__ __forceinline__ u64t pack2(float lo, float hi) {
    u64t d;
    asm("mov.b64 %0, {%1, %2};" : "=l"(d) : "f"(lo), "f"(hi));
    return d;
}
__device__ __forceinline__ u64t dup2(float v) { return pack2(v, v); }
__device__ __forceinline__ void unpack2(u64t v, float& lo, float& hi) {
    asm("mov.b64 {%0, %1}, %2;" : "=f"(lo), "=f"(hi) : "l"(v));
}
__device__ __forceinline__ void named_bar(int id, int cnt) {
    asm volatile("bar.sync %0, %1;" :: "r"(id), "r"(cnt) : "memory");
}

// ---------------- device scratch ----------------
// feature buffers in component-major tile layout:
//   buf[ ((b*BPB + blk)*CH + ch) * 48 + comp*16 + p ]
__device__ float g_net0[NB * BPB * 64 * 48];
__device__ float g_net1[NB * BPB * 128 * 48];
__device__ float g_net2[NB * BPB * 128 * 48];

__device__ float g_Wn_pos[64 * 3];
__device__ float g_WD1[64 * 128 * 2];    // [i][o][{w,d}] normalized W1 / D1
__device__ float g_WD2[128 * 128 * 2];   // W2/D2 cols [0,128)
__device__ float g_WD3[128 * 128 * 2];
__device__ float g_WD2B[128 * 128 * 2];  // W2/D2 cols [128,256) (pooled half)
__device__ float g_WD3B[128 * 128 * 2];

__device__ float g_part1[NB * BPB * 384];
__device__ float g_part2[NB * BPB * 384];
__device__ float g_part3[NB * BPB * 384];
__device__ float g_biasP2[NB * 384];
__device__ float g_biasD2[NB * 384];
__device__ float g_biasP3[NB * 384];
__device__ float g_biasD3[NB * 384];

// ---------------- prep A: row-normalize W matrices (block per row) ----------------
__global__ void __launch_bounds__(128)
prep_norm_kernel(const float* __restrict__ Wpos, const float* __restrict__ W1,
                 const float* __restrict__ W2,   const float* __restrict__ W3) {
    __shared__ float sr[128];
    int tid = threadIdx.x;
    int bx = blockIdx.x;
    if (bx == 0) {
        if (tid < 64) {
            const float* s = Wpos + tid * 3;
            float sum = s[0] + s[1] + s[2];
            for (int i = 0; i < 3; i++) g_Wn_pos[tid * 3 + i] = s[i] / sum;
        }
        return;
    }
    if (bx <= 128) {
        int r = bx - 1;
        float v = (tid < 64) ? W1[r * 64 + tid] : 0.f;
        sr[tid] = v;
        __syncthreads();
        for (int s = 64; s > 0; s >>= 1) {
            if (tid < s) sr[tid] += sr[tid + s];
            __syncthreads();
        }
        float inv = 1.f / sr[0];
        if (tid < 64) g_WD1[(tid * 128 + r) * 2] = v * inv;
        return;
    }
    const float* W  = (bx <= 256) ? W2 : W3;
    float* WD  = (bx <= 256) ? g_WD2  : g_WD3;
    float* WDB = (bx <= 256) ? g_WD2B : g_WD3B;
    int r = (bx <= 256) ? (bx - 129) : (bx - 257);
    float v0 = W[r * 256 + tid];
    float v1 = W[r * 256 + tid + 128];
    sr[tid] = v0 + v1;
    __syncthreads();
    for (int s = 64; s > 0; s >>= 1) {
        if (tid < s) sr[tid] += sr[tid + s];
        __syncthreads();
    }
    float inv = 1.f / sr[0];
    WD [(tid * 128 + r) * 2] = v0 * inv;
    WDB[(tid * 128 + r) * 2] = v1 * inv;
}

// ---------------- prep B: transpose D matrices into interleaved slots ----------------
__global__ void __launch_bounds__(256)
prep_transpose_kernel(const float* __restrict__ D1, const float* __restrict__ D2,
                      const float* __restrict__ D3) {
    int idx = blockIdx.x * 256 + threadIdx.x;
    if (idx < 8192) {                                   // D1: [128][64]
        int i = idx >> 7, rr = idx & 127;
        g_WD1[(i * 128 + rr) * 2 + 1] = D1[rr * 64 + i];
    } else if (idx < 8192 + 16384) {                    // D2 cols [0,128)
        int t = idx - 8192;
        int i = t >> 7, rr = t & 127;
        g_WD2[(i * 128 + rr) * 2 + 1] = D2[rr * 256 + i];
    } else if (idx < 8192 + 32768) {                    // D2 cols [128,256)
        int t = idx - 8192 - 16384;
        int i = t >> 7, rr = t & 127;
        g_WD2B[(i * 128 + rr) * 2 + 1] = D2[rr * 256 + 128 + i];
    } else if (idx < 8192 + 32768 + 16384) {            // D3 cols [0,128)
        int t = idx - 8192 - 32768;
        int i = t >> 7, rr = t & 127;
        g_WD3[(i * 128 + rr) * 2 + 1] = D3[rr * 256 + i];
    } else if (idx < 8192 + 65536) {                    // D3 cols [128,256)
        int t = idx - 8192 - 32768 - 16384;
        int i = t >> 7, rr = t & 127;
        g_WD3B[(i * 128 + rr) * 2 + 1] = D3[rr * 256 + 128 + i];
    }
}

// ---------------- fused kNN + edge features + pos layer + mean-k (R7 winner) ----------------
__global__ void __launch_bounds__(256)
knn_edge_kernel(const float* __restrict__ pc, const float* __restrict__ Dpos) {
    __shared__ float4 sq[NPTS];
    __shared__ float wsh[64 * 3], dsh[64 * 3];
    __shared__ float nbx[8][24], nby[8][24], nbz[8][24];

    int b = blockIdx.y;
    const float* pb = pc + b * NPTS * 3;
    for (int m = threadIdx.x; m < NPTS; m += 256) {
        float x = pb[m * 3 + 0], y = pb[m * 3 + 1], z = pb[m * 3 + 2];
        sq[m] = make_float4(x, y, z, x * x + y * y + z * z);
    }
    for (int t = threadIdx.x; t < 192; t += 256) {
        wsh[t] = g_Wn_pos[t];
        dsh[t] = Dpos[t];
    }
    __syncthreads();

    int wid  = threadIdx.x >> 5;
    int lane = threadIdx.x & 31;
    int n = blockIdx.x * 8 + wid;
    float4 c = sq[n];

    float val = -3.4e38f;
    int   idx = 0;
    float tau = -3.4e38f;

#pragma unroll 1
    for (int r = 0; r < NPTS / 32; r++) {
        int m = r * 32 + lane;
        float4 q = sq[m];
        float d = 2.f * (c.x * q.x + c.y * q.y + c.z * q.z) - c.w - q.w;
        unsigned mask = __ballot_sync(0xffffffffu, d > tau);
        while (mask) {
            int src = __ffs(mask) - 1;
            mask &= mask - 1;
            float dc = __shfl_sync(0xffffffffu, d, src);
            if (dc > tau) {
                int mc = r * 32 + src;
                float vup = __shfl_up_sync(0xffffffffu, val, 1);
                int   iup = __shfl_up_sync(0xffffffffu, idx, 1);
                bool cw = dc > val;
                float t  = cw ? dc : val;
                int   ti = cw ? mc : idx;
                bool up = (lane > 0) && (vup < t);
                val = up ? vup : t;
                idx = up ? iup : ti;
                tau = __shfl_sync(0xffffffffu, val, KNN - 1);
            }
        }
    }

    if (lane < KNN) {
        float4 q = sq[idx];
        nbx[wid][lane] = q.x; nby[wid][lane] = q.y; nbz[wid][lane] = q.z;
    }
    __syncwarp();

    float cx = c.x, cy = c.y, cz = c.z;
    u64t cx2 = dup2(cx),  cy2 = dup2(cy),  cz2 = dup2(cz);
    u64t ncx2 = dup2(-cx), ncy2 = dup2(-cy), ncz2 = dup2(-cz);

    u64t w0_2[2], w2_2[2], d0_2[2], d2_2[2];
    u64t A2[2][3], B2[2][3];
    u64t acc[2][3];
#pragma unroll
    for (int u = 0; u < 2; u++) {
        int ch = lane + u * 32;
        float w0 = wsh[ch * 3 + 0], w1 = wsh[ch * 3 + 1], w2v = wsh[ch * 3 + 2];
        float d0 = dsh[ch * 3 + 0], d1 = dsh[ch * 3 + 1], d2v = dsh[ch * 3 + 2];
        w0_2[u] = dup2(w0); w2_2[u] = dup2(w2v);
        d0_2[u] = dup2(d0); d2_2[u] = dup2(d2v);
        float aw = w1 - w0, ad = d1 - d0;
        A2[u][0] = dup2(aw * cx); A2[u][1] = dup2(aw * cy); A2[u][2] = dup2(aw * cz);
        B2[u][0] = dup2(ad * cx); B2[u][1] = dup2(ad * cy); B2[u][2] = dup2(ad * cz);
        acc[u][0] = 0ull; acc[u][1] = 0ull; acc[u][2] = 0ull;
    }

#pragma unroll
    for (int kp = 0; kp < KNN / 2; kp++) {
        u64t nx2 = *(const u64t*)(&nbx[wid][kp * 2]);
        u64t ny2 = *(const u64t*)(&nby[wid][kp * 2]);
        u64t nz2 = *(const u64t*)(&nbz[wid][kp * 2]);
        u64t r0 = fma2(nz2, ncy2, mul2(ny2, cz2));
        u64t r1 = fma2(nx2, ncz2, mul2(nz2, cx2));
        u64t r2 = fma2(ny2, ncx2, mul2(nx2, cy2));
#pragma unroll
        for (int u = 0; u < 2; u++) {
            u64t p0 = fma2(w0_2[u], nx2, fma2(w2_2[u], r0, A2[u][0]));
            u64t p1 = fma2(w0_2[u], ny2, fma2(w2_2[u], r1, A2[u][1]));
            u64t p2 = fma2(w0_2[u], nz2, fma2(w2_2[u], r2, A2[u][2]));
            u64t q0 = fma2(d0_2[u], nx2, fma2(d2_2[u], r0, B2[u][0]));
            u64t q1 = fma2(d0_2[u], ny2, fma2(d2_2[u], r1, B2[u][1]));
            u64t q2 = fma2(d0_2[u], nz2, fma2(d2_2[u], r2, B2[u][2]));
            u64t dot2 = fma2(p2, q2, fma2(p1, q1, mul2(p0, q0)));
            u64t dns2 = fma2(q2, q2, fma2(q1, q1, mul2(q0, q0)));
            float dlo, dhi, slo, shi;
            unpack2(dot2, dlo, dhi);
            unpack2(dns2, slo, shi);
            float ntlo = (dlo < 0.f) ? -__fdividef(dlo, slo + EPSV) : 0.f;
            float nthi = (dhi < 0.f) ? -__fdividef(dhi, shi + EPSV) : 0.f;
            u64t nt2 = pack2(ntlo, nthi);
            acc[u][0] = fma2(nt2, q0, add2(acc[u][0], p0));
            acc[u][1] = fma2(nt2, q1, add2(acc[u][1], p1));
            acc[u][2] = fma2(nt2, q2, add2(acc[u][2], p2));
        }
    }

    const float inv = 1.f / (float)KNN;
    int blk = n >> 4, pp = n & 15;
#pragma unroll
    for (int u = 0; u < 2; u++) {
        int ch = lane + u * 32;
        float* dst = g_net0 + ((long)((b * BPB + blk) * 64 + ch)) * 48 + pp;
#pragma unroll
        for (int cc = 0; cc < 3; cc++) {
            float lo, hi;
            unpack2(acc[u][cc], lo, hi);
            dst[cc * 16] = (lo + hi) * inv;
        }
    }
}

// ---------------- layer64: 2 outputs/thread, reg-staged double buffer (R7 winner) ----------------
__global__ void __launch_bounds__(256)
layer64_kernel(const float* __restrict__ in, const float* __restrict__ WDg,
               float* __restrict__ out, float* __restrict__ part, int stride) {
    extern __shared__ float smem[];
    float* WDs = smem;                 // [64][128] float2
    float* xs  = WDs + 64 * 256;       // [64][3][16]
    constexpr int PF = 3;

    int tid = threadIdx.x;
    int q = tid >> 2;
    int g = tid & 3;

    for (int t = tid; t < 64 * 128; t += 256)
        ((float2*)WDs)[t] = ((const float2*)WDg)[t];

    int job = blockIdx.x;
    float4 pf[PF];
    {
        const float4* ip = (const float4*)(in + (long)job * 64 * 48);
#pragma unroll
        for (int k = 0; k < PF; k++) pf[k] = ip[tid + k * 256];
    }
    __syncthreads();

#pragma unroll 1
    for (; job < NJOBS; job += stride) {
#pragma unroll
        for (int k = 0; k < PF; k++) ((float4*)xs)[tid + k * 256] = pf[k];
        __syncthreads();

        int nj = job + stride;
        if (nj < NJOBS) {
            const float4* ip = (const float4*)(in + (long)nj * 64 * 48);
#pragma unroll
            for (int k = 0; k < PF; k++) pf[k] = ip[tid + k * 256];
        }

        u64t aP[2][3][2], aD[2][3][2];
#pragma unroll
        for (int oo = 0; oo < 2; oo++)
#pragma unroll
            for (int c = 0; c < 3; c++) {
                aP[oo][c][0] = 0ull; aP[oo][c][1] = 0ull;
                aD[oo][c][0] = 0ull; aD[oo][c][1] = 0ull;
            }

#pragma unroll 2
        for (int i = 0; i < 64; ++i) {
            float2 wd0 = ((const float2*)WDs)[i * 128 + q];
            float2 wd1 = ((const float2*)WDs)[i * 128 + 64 + q];
            u64t w0 = dup2(wd0.x), d0 = dup2(wd0.y);
            u64t w1 = dup2(wd1.x), d1 = dup2(wd1.y);
#pragma unroll
            for (int c = 0; c < 3; c++) {
                ulonglong2 X = *(const ulonglong2*)(xs + i * 48 + c * 16 + g * 4);
                aP[0][c][0] = fma2(w0, X.x, aP[0][c][0]);
                aP[0][c][1] = fma2(w0, X.y, aP[0][c][1]);
                aD[0][c][0] = fma2(d0, X.x, aD[0][c][0]);
                aD[0][c][1] = fma2(d0, X.y, aD[0][c][1]);
                aP[1][c][0] = fma2(w1, X.x, aP[1][c][0]);
                aP[1][c][1] = fma2(w1, X.y, aP[1][c][1]);
                aD[1][c][0] = fma2(d1, X.x, aD[1][c][0]);
                aD[1][c][1] = fma2(d1, X.y, aD[1][c][1]);
            }
        }

#pragma unroll
        for (int oo = 0; oo < 2; oo++) {
            int o = q + oo * 64;
            float px[3][4], dx[3][4];
#pragma unroll
            for (int c = 0; c < 3; c++) {
                unpack2(aP[oo][c][0], px[c][0], px[c][1]);
                unpack2(aP[oo][c][1], px[c][2], px[c][3]);
                unpack2(aD[oo][c][0], dx[c][0], dx[c][1]);
                unpack2(aD[oo][c][1], dx[c][2], dx[c][3]);
            }
            float qv[3][4];
            float s0 = 0.f, s1 = 0.f, s2 = 0.f;
#pragma unroll
            for (int p = 0; p < 4; p++) {
                float q0 = px[0][p], q1 = px[1][p], q2 = px[2][p];
                float e0 = dx[0][p], e1 = dx[1][p], e2 = dx[2][p];
                float dot = q0 * e0 + q1 * e1 + q2 * e2;
                if (dot < 0.f) {
                    float dns = e0 * e0 + e1 * e1 + e2 * e2;
                    float tt2 = __fdividef(dot, dns + EPSV);
                    q0 -= tt2 * e0; q1 -= tt2 * e1; q2 -= tt2 * e2;
                }
                qv[0][p] = q0; qv[1][p] = q1; qv[2][p] = q2;
                s0 += q0; s1 += q1; s2 += q2;
            }
            float4* out4 = (float4*)(out + ((long)(job * 128 + o)) * 48);
#pragma unroll
            for (int c = 0; c < 3; c++)
                out4[c * 4 + g] = make_float4(qv[c][0], qv[c][1], qv[c][2], qv[c][3]);

            s0 += __shfl_xor_sync(0xffffffffu, s0, 1);
            s1 += __shfl_xor_sync(0xffffffffu, s1, 1);
            s2 += __shfl_xor_sync(0xffffffffu, s2, 1);
            s0 += __shfl_xor_sync(0xffffffffu, s0, 2);
            s1 += __shfl_xor_sync(0xffffffffu, s1, 2);
            s2 += __shfl_xor_sync(0xffffffffu, s2, 2);
            if (g == 0) {
                float* dst = part + (long)job * 384 + o * 3;
                dst[0] = s0; dst[1] = s1; dst[2] = s2;
            }
        }
        __syncthreads();
    }
}

// ---------------- layer128: 512 threads, shared WD, independent halves via named barriers ----------------
// Half h = tid>>8 walks jobs (2*blockIdx.x + h) + k*296 with its own xs buffer,
// synced by bar.sync(1+h, 256) — no cross-half phase coupling.
template <bool STORE>
__global__ void __launch_bounds__(512)
layer128_kernel(const float* __restrict__ in, const float* __restrict__ WDg,
                const float* __restrict__ biasP, const float* __restrict__ biasD,
                float* __restrict__ out, float* __restrict__ part) {
    extern __shared__ float smem[];
    float* WDs = smem;                  // [128][128] float2 = 128 KB
    float* xs0 = WDs + 128 * 256;       // [2][128][3][16] = 48 KB
    constexpr int PF = 6;

    int tid = threadIdx.x;
    int h  = tid >> 8;
    int lt = tid & 255;
    int q = lt >> 2;
    int g = lt & 3;
    float* xs = xs0 + h * 128 * 48;
    int bar = 1 + h;

    for (int t = tid; t < 128 * 128; t += 512)
        ((float2*)WDs)[t] = ((const float2*)WDg)[t];

    int job = blockIdx.x * 2 + h;
    float4 pf[PF];
    {
        const float4* ip = (const float4*)(in + (long)job * 128 * 48);
#pragma unroll
        for (int k = 0; k < PF; k++) pf[k] = ip[lt + k * 256];
    }
    __syncthreads();   // WD visible to both halves

#pragma unroll 1
    for (; job < NJOBS; job += 296) {
#pragma unroll
        for (int k = 0; k < PF; k++) ((float4*)xs)[lt + k * 256] = pf[k];
        named_bar(bar, 256);

        int nj = job + 296;
        if (nj < NJOBS) {
            const float4* ip = (const float4*)(in + (long)nj * 128 * 48);
#pragma unroll
            for (int k = 0; k < PF; k++) pf[k] = ip[lt + k * 256];
        }

        int b = job >> 7;
        u64t aP[2][3][2], aD[2][3][2];
#pragma unroll
        for (int oo = 0; oo < 2; oo++) {
            int o = q + oo * 64;
#pragma unroll
            for (int c = 0; c < 3; c++) {
                u64t bp = dup2(biasP[b * 384 + o * 3 + c]);
                u64t bd = dup2(biasD[b * 384 + o * 3 + c]);
                aP[oo][c][0] = bp; aP[oo][c][1] = bp;
                aD[oo][c][0] = bd; aD[oo][c][1] = bd;
            }
        }

#pragma unroll 2
        for (int i = 0; i < 128; ++i) {
            float2 wd0 = ((const float2*)WDs)[i * 128 + q];
            float2 wd1 = ((const float2*)WDs)[i * 128 + 64 + q];
            u64t w0 = dup2(wd0.x), d0 = dup2(wd0.y);
            u64t w1 = dup2(wd1.x), d1 = dup2(wd1.y);
#pragma unroll
            for (int c = 0; c < 3; c++) {
                ulonglong2 X = *(const ulonglong2*)(xs + i * 48 + c * 16 + g * 4);
                aP[0][c][0] = fma2(w0, X.x, aP[0][c][0]);
                aP[0][c][1] = fma2(w0, X.y, aP[0][c][1]);
                aD[0][c][0] = fma2(d0, X.x, aD[0][c][0]);
                aD[0][c][1] = fma2(d0, X.y, aD[0][c][1]);
                aP[1][c][0] = fma2(w1, X.x, aP[1][c][0]);
                aP[1][c][1] = fma2(w1, X.y, aP[1][c][1]);
                aD[1][c][0] = fma2(d1, X.x, aD[1][c][0]);
                aD[1][c][1] = fma2(d1, X.y, aD[1][c][1]);
            }
        }

#pragma unroll
        for (int oo = 0; oo < 2; oo++) {
            int o = q + oo * 64;
            float px[3][4], dx[3][4];
#pragma unroll
            for (int c = 0; c < 3; c++) {
                unpack2(aP[oo][c][0], px[c][0], px[c][1]);
                unpack2(aP[oo][c][1], px[c][2], px[c][3]);
                unpack2(aD[oo][c][0], dx[c][0], dx[c][1]);
                unpack2(aD[oo][c][1], dx[c][2], dx[c][3]);
            }
            float qv[3][4];
            float s0 = 0.f, s1 = 0.f, s2 = 0.f;
#pragma unroll
            for (int p = 0; p < 4; p++) {
                float q0 = px[0][p], q1 = px[1][p], q2 = px[2][p];
                float e0 = dx[0][p], e1 = dx[1][p], e2 = dx[2][p];
                float dot = q0 * e0 + q1 * e1 + q2 * e2;
                if (dot < 0.f) {
                    float dns = e0 * e0 + e1 * e1 + e2 * e2;
                    float tt2 = __fdividef(dot, dns + EPSV);
                    q0 -= tt2 * e0; q1 -= tt2 * e1; q2 -= tt2 * e2;
                }
                qv[0][p] = q0; qv[1][p] = q1; qv[2][p] = q2;
                s0 += q0; s1 += q1; s2 += q2;
            }
            if (STORE) {
                float4* out4 = (float4*)(out + ((long)(job * 128 + o)) * 48);
#pragma unroll
                for (int c = 0; c < 3; c++)
                    out4[c * 4 + g] = make_float4(qv[c][0], qv[c][1], qv[c][2], qv[c][3]);
            }
            s0 += __shfl_xor_sync(0xffffffffu, s0, 1);
            s1 += __shfl_xor_sync(0xffffffffu, s1, 1);
            s2 += __shfl_xor_sync(0xffffffffu, s2, 1);
            s0 += __shfl_xor_sync(0xffffffffu, s0, 2);
            s1 += __shfl_xor_sync(0xffffffffu, s1, 2);
            s2 += __shfl_xor_sync(0xffffffffu, s2, 2);
            if (g == 0) {
                float* dst = part + (long)job * 384 + o * 3;
                dst[0] = s0; dst[1] = s1; dst[2] = s2;
            }
        }
        named_bar(bar, 256);   // half's xs readers done before next publish
    }
}

// ---------------- bias from pooled mean: coalesced interleaved weights ----------------
__global__ void __launch_bounds__(128)
bias_kernel(const float* __restrict__ part, const float* __restrict__ WDb,
            float* __restrict__ biasP, float* __restrict__ biasD) {
    __shared__ float mean[384];
    int b = blockIdx.x;
    int tid = threadIdx.x;  // 128
    for (int t = tid; t < 384; t += 128) {
        float s = 0.f;
#pragma unroll 16
        for (int blk = 0; blk < BPB; blk++) s += part[((long)(b * BPB + blk)) * 384 + t];
        mean[t] = s * (1.f / (float)NPTS);
    }
    __syncthreads();
    int o = tid;
    float p0 = 0.f, p1 = 0.f, p2 = 0.f, d0 = 0.f, d1 = 0.f, d2 = 0.f;
#pragma unroll 8
    for (int i = 0; i < 128; i++) {
        float2 wd = ((const float2*)WDb)[i * 128 + o];
        float m0 = mean[i * 3 + 0], m1 = mean[i * 3 + 1], m2 = mean[i * 3 + 2];
        p0 += wd.x * m0;  p1 += wd.x * m1;  p2 += wd.x * m2;
        d0 += wd.y * m0;  d1 += wd.y * m1;  d2 += wd.y * m2;
    }
    biasP[b * 384 + o * 3 + 0] = p0;
    biasP[b * 384 + o * 3 + 1] = p1;
    biasP[b * 384 + o * 3 + 2] = p2;
    biasD[b * 384 + o * 3 + 0] = d0;
    biasD[b * 384 + o * 3 + 1] = d1;
    biasD[b * 384 + o * 3 + 2] = d2;
}

// ---------------- final mean over N -> output [B,384] ----------------
__global__ void __launch_bounds__(384)
final_kernel(const float* __restrict__ part, float* __restrict__ outp) {
    int b = blockIdx.x;
    int t = threadIdx.x;
    float s = 0.f;
#pragma unroll 16
    for (int blk = 0; blk < BPB; blk++) s += part[((long)(b * BPB + blk)) * 384 + t];
    outp[b * 384 + t] = s * (1.f / (float)NPTS);
}

// ---------------- launch ----------------
extern "C" void kernel_launch(void* const* d_in, const int* in_sizes, int n_in,
                              void* d_out, int out_size) {
    const float* pc   = (const float*)d_in[0];
    const float* Wpos = (const float*)d_in[1];
    const float* Dpos = (const float*)d_in[2];
    const float* W1   = (const float*)d_in[3];
    const float* D1   = (const float*)d_in[4];
    const float* W2   = (const float*)d_in[5];
    const float* D2   = (const float*)d_in[6];
    const float* W3   = (const float*)d_in[7];
    const float* D3   = (const float*)d_in[8];
    float* outp = (float*)d_out;

    int smem1 = 64 * 256 * 4 + 64 * 48 * 4;             //  77824 B -> 2 blocks/SM
    int smem2 = 128 * 256 * 4 + 2 * 128 * 48 * 4;       // 180224 B -> 1 block/SM, 16 warps
    cudaFuncSetAttribute(layer64_kernel,
                         cudaFuncAttributeMaxDynamicSharedMemorySize, smem1);
    cudaFuncSetAttribute(layer128_kernel<true>,
                         cudaFuncAttributeMaxDynamicSharedMemorySize, smem2);
    cudaFuncSetAttribute(layer128_kernel<false>,
                         cudaFuncAttributeMaxDynamicSharedMemorySize, smem2);

    void *net0p, *net1p, *net2p;
    void *wd1, *wd2, *wd3, *wd2b, *wd3b;
    void *part1, *part2, *part3, *bp2, *bd2, *bp3, *bd3;
    cudaGetSymbolAddress(&net0p, g_net0);
    cudaGetSymbolAddress(&net1p, g_net1);
    cudaGetSymbolAddress(&net2p, g_net2);
    cudaGetSymbolAddress(&wd1, g_WD1);
    cudaGetSymbolAddress(&wd2, g_WD2);
    cudaGetSymbolAddress(&wd3, g_WD3);
    cudaGetSymbolAddress(&wd2b, g_WD2B);
    cudaGetSymbolAddress(&wd3b, g_WD3B);
    cudaGetSymbolAddress(&part1, g_part1);
    cudaGetSymbolAddress(&part2, g_part2);
    cudaGetSymbolAddress(&part3, g_part3);
    cudaGetSymbolAddress(&bp2, g_biasP2);
    cudaGetSymbolAddress(&bd2, g_biasD2);
    cudaGetSymbolAddress(&bp3, g_biasP3);
    cudaGetSymbolAddress(&bd3, g_biasD3);

    prep_norm_kernel<<<385, 128>>>(Wpos, W1, W2, W3);
    prep_transpose_kernel<<<288, 256>>>(D1, D2, D3);
    knn_edge_kernel<<<dim3(NPTS / 8, NB), 256>>>(pc, Dpos);

    layer64_kernel<<<296, 256, smem1>>>(
        (const float*)net0p, (const float*)wd1,
        (float*)net1p, (float*)part1, 296);

    bias_kernel<<<NB, 128>>>((const float*)part1, (const float*)wd2b,
                             (float*)bp2, (float*)bd2);

    layer128_kernel<true><<<148, 512, smem2>>>(
        (const float*)net1p, (const float*)wd2,
        (const float*)bp2, (const float*)bd2, (float*)net2p, (float*)part2);

    bias_kernel<<<NB, 128>>>((const float*)part2, (const float*)wd3b,
                             (float*)bp3, (float*)bd3);

    layer128_kernel<false><<<148, 512, smem2>>>(
        (const float*)net2p, (const float*)wd3,
        (const float*)bp3, (const float*)bd3, nullptr, (float*)part3);

    final_kernel<<<NB, 384>>>((const float*)part3, outp);
}